// round 15
// baseline (speedup 1.0000x reference)
#include <cuda_runtime.h>
#include <cuda_bf16.h>
#include <cstdint>
#include <math_constants.h>

#define B_ 4
#define S_ 2048
#define E_ 1024
#define H_ 16
#define D_ 64
#define M_ (B_*S_)

// ---------------- scratch (static device globals; no allocation) ----------------
__device__ __nv_bfloat16 g_x[(size_t)M_*E_];
__device__ __nv_bfloat16 g_wq[(size_t)E_*E_];
__device__ __nv_bfloat16 g_wk[(size_t)E_*E_];
__device__ __nv_bfloat16 g_wv[(size_t)E_*E_];
__device__ __nv_bfloat16 g_wo[(size_t)E_*E_];
__device__ __nv_bfloat16 g_q[(size_t)B_*H_*S_*D_];   // pre-scaled by log2(e)/8
__device__ __nv_bfloat16 g_k[(size_t)B_*H_*S_*D_];
__device__ __nv_bfloat16 g_v[(size_t)B_*H_*S_*D_];
__device__ __nv_bfloat16 g_attn[(size_t)M_*E_];
__device__ float g_y[(size_t)M_*E_];

// ---------------- helpers ----------------
__device__ __forceinline__ unsigned pkbf(float lo, float hi){
    unsigned r; asm("cvt.rn.bf16x2.f32 %0, %1, %2;" : "=r"(r) : "f"(hi), "f"(lo)); return r;
}
__device__ __forceinline__ float ex2(float x){
    float r; asm("ex2.approx.f32 %0, %1;" : "=f"(r) : "f"(x)); return r;
}
__device__ __forceinline__ void mma16(float* c, const unsigned* a, const unsigned* b){
    asm volatile(
        "mma.sync.aligned.m16n8k16.row.col.f32.bf16.bf16.f32 "
        "{%0,%1,%2,%3},{%4,%5,%6,%7},{%8,%9},{%0,%1,%2,%3};"
        : "+f"(c[0]), "+f"(c[1]), "+f"(c[2]), "+f"(c[3])
        : "r"(a[0]), "r"(a[1]), "r"(a[2]), "r"(a[3]), "r"(b[0]), "r"(b[1]));
}
__device__ __forceinline__ unsigned sptr(const void* p){
    return (unsigned)__cvta_generic_to_shared(p);
}
__device__ __forceinline__ void ldsm4(unsigned& r0, unsigned& r1, unsigned& r2, unsigned& r3, unsigned a){
    asm volatile("ldmatrix.sync.aligned.m8n8.x4.shared.b16 {%0,%1,%2,%3}, [%4];"
        : "=r"(r0), "=r"(r1), "=r"(r2), "=r"(r3) : "r"(a));
}
__device__ __forceinline__ void ldsm4t(unsigned& r0, unsigned& r1, unsigned& r2, unsigned& r3, unsigned a){
    asm volatile("ldmatrix.sync.aligned.m8n8.x4.trans.shared.b16 {%0,%1,%2,%3}, [%4];"
        : "=r"(r0), "=r"(r1), "=r"(r2), "=r"(r3) : "r"(a));
}
__device__ __forceinline__ void cpa16(unsigned s, const void* g){
    asm volatile("cp.async.cg.shared.global [%0], [%1], 16;" :: "r"(s), "l"(g));
}
__device__ __forceinline__ void cpa_commit(){ asm volatile("cp.async.commit_group;"); }
template<int N> __device__ __forceinline__ void cpa_wait(){
    asm volatile("cp.async.wait_group %0;" :: "n"(N));
}

// ---------------- fused fp32 -> bf16 conversion (inputs + 4 weights) ----------------
#define NX4 ((M_*E_)/4)
#define NW4 ((E_*E_)/4)
__global__ void __launch_bounds__(256)
cvt_kernel(const float* __restrict__ x,  const float* __restrict__ wq,
           const float* __restrict__ wk, const float* __restrict__ wv,
           const float* __restrict__ wo)
{
    int i = blockIdx.x * blockDim.x + threadIdx.x;
    const float* src; __nv_bfloat16* dst; int off;
    if (i < NX4) { src = x; dst = g_x; off = i; }
    else {
        int j = i - NX4; int w = j / NW4; off = j - w*NW4;
        src = (w == 0) ? wq : (w == 1) ? wk : (w == 2) ? wv : wo;
        dst = (w == 0) ? g_wq : (w == 1) ? g_wk : (w == 2) ? g_wv : g_wo;
    }
    float4 v = reinterpret_cast<const float4*>(src)[off];
    reinterpret_cast<uint2*>(dst)[off] = make_uint2(pkbf(v.x, v.y), pkbf(v.z, v.w));
}

// ---------------- GEMM: 128x128x32 tile, 4 warps (2x2), warp tile 64x64 ----------------
// 5-stage cp.async (3-tile prefetch slack), 2 CTAs/SM.
#define GSTAGES 5
#define AS_ELEM 5120   // 128*40
#define BS_ELEM 4352   // 32*136
#define GEMM_SMEM ((GSTAGES*(AS_ELEM + BS_ELEM)) * 2)
#define ASO(st) ((st)*AS_ELEM)
#define BSO(st) (GSTAGES*AS_ELEM + (st)*BS_ELEM)

// MODE 0: fused QKV (grid.x = 24: [qkv sel][8 col blocks]); MODE 3: O-proj
template<int MODE>
__global__ void __launch_bounds__(128, 2)
gemm_kernel(const float* __restrict__ b0p, const float* __restrict__ b1p,
            const float* __restrict__ b2p, const float* __restrict__ resid)
{
    extern __shared__ __align__(16) __nv_bfloat16 sm[];

    const int tid = threadIdx.x, lane = tid & 31;
    const int g = lane >> 2, t4 = lane & 3;
    const int wid = tid >> 5, wm = wid & 1, wn = wid >> 1;   // 2 x 2 warp grid
    const int sel = (MODE == 0) ? (blockIdx.x >> 3) : 0;
    const int bm = blockIdx.y * 128, bn = (MODE == 0) ? (blockIdx.x & 7) * 128 : blockIdx.x * 128;

    const __nv_bfloat16* Ap = (MODE == 3) ? g_attn : g_x;
    const __nv_bfloat16* Wp = (MODE == 3) ? g_wo :
                              (sel == 0) ? g_wq : (sel == 1) ? g_wk : g_wv;
    const float* bias = (MODE == 3) ? b0p : (sel == 0) ? b0p : (sel == 1) ? b1p : b2p;

    float acc[4][8][4] = {};

    #define G_ISSUE(KT, ST) { \
        _Pragma("unroll") for (int i = 0; i < 4; i++){ \
            int idx = tid + 128*i; \
            int ar = idx >> 2, ac = (idx & 3) * 8; \
            cpa16(sptr(&sm[ASO(ST) + ar*40 + ac]), Ap + (size_t)(bm + ar)*E_ + (KT) + ac); \
            int br = idx >> 4, bc = (idx & 15) * 8; \
            cpa16(sptr(&sm[BSO(ST) + br*136 + bc]), Wp + (size_t)((KT) + br)*E_ + bn + bc); \
        } \
        cpa_commit(); }

    G_ISSUE(0, 0);
    G_ISSUE(32, 1);
    G_ISSUE(64, 2);
    G_ISSUE(96, 3);

    cpa_wait<3>();
    __syncthreads();

    #pragma unroll 1
    for (int kt = 0; kt < 32; kt++){
        const int st = kt % 5;
        if (kt + 4 < 32) G_ISSUE((kt+4)*32, (kt+4) % 5);

        #pragma unroll
        for (int s = 0; s < 2; s++){
            unsigned af[4][4];
            #pragma unroll
            for (int mi = 0; mi < 4; mi++)
                ldsm4(af[mi][0], af[mi][1], af[mi][2], af[mi][3],
                      sptr(&sm[ASO(st) + (wm*64 + mi*16 + (lane & 15))*40 + s*16 + ((lane & 16) >> 1)]));
            unsigned bfr[8][2];
            #pragma unroll
            for (int nb = 0; nb < 4; nb++)
                ldsm4t(bfr[2*nb][0], bfr[2*nb][1], bfr[2*nb+1][0], bfr[2*nb+1][1],
                       sptr(&sm[BSO(st) + (s*16 + (lane & 15))*136 + wn*64 + nb*16 + ((lane & 16) >> 1)]));
            #pragma unroll
            for (int mi = 0; mi < 4; mi++)
            #pragma unroll
            for (int ni = 0; ni < 8; ni++)
                mma16(acc[mi][ni], af[mi], bfr[ni]);
        }

        if (kt + 1 < 32){
            cpa_wait<3>();
            __syncthreads();
        }
    }
    #undef G_ISSUE

    const float qsc = (MODE == 0 && sel == 0) ? 0.125f*1.44269504f : 1.0f;
    #pragma unroll
    for (int mi = 0; mi < 4; mi++)
    #pragma unroll
    for (int ni = 0; ni < 8; ni++){
        int row = bm + wm*64 + mi*16 + g;
        int col = bn + wn*64 + ni*8 + t4*2;
        float b0 = bias[col], b1 = bias[col+1];
        if (MODE == 3){
            float2 r0 = *reinterpret_cast<const float2*>(&resid[(size_t)row*E_ + col]);
            float2 r1 = *reinterpret_cast<const float2*>(&resid[(size_t)(row+8)*E_ + col]);
            *reinterpret_cast<float2*>(&g_y[(size_t)row*E_ + col]) =
                make_float2(acc[mi][ni][0] + b0 + r0.x, acc[mi][ni][1] + b1 + r0.y);
            *reinterpret_cast<float2*>(&g_y[(size_t)(row+8)*E_ + col]) =
                make_float2(acc[mi][ni][2] + b0 + r1.x, acc[mi][ni][3] + b1 + r1.y);
        } else {
            __nv_bfloat16* op = (sel == 0) ? g_q : (sel == 1) ? g_k : g_v;
            int h = col >> 6, d = col & 63;
            unsigned p0 = pkbf((acc[mi][ni][0] + b0)*qsc, (acc[mi][ni][1] + b1)*qsc);
            unsigned p1 = pkbf((acc[mi][ni][2] + b0)*qsc, (acc[mi][ni][3] + b1)*qsc);
            int b = row >> 11, s0 = row & (S_-1);
            size_t base = (((size_t)(b*H_ + h))*S_);
            *reinterpret_cast<unsigned*>(&op[(base + s0    )*D_ + d]) = p0;
            *reinterpret_cast<unsigned*>(&op[(base + s0 + 8)*D_ + d]) = p1;
        }
    }
}

// ---------------- flash attention: Br=128, Bc=64, 4 warps x 32 Q-rows ----------------
// R13 structure; 4 KV buffers, 3-tile prefetch distance. l via ones-column MMA.
#define FQ0 0
#define FK0 9216
#define FV0 27648
#define FSTR 72
#define KVBUF 4608
#define NT (S_/64)
#define FLASH_SMEM ((FV0 + 4*KVBUF) * 2)

__global__ void __launch_bounds__(128, 2)
flash_kernel()
{
    extern __shared__ __align__(16) __nv_bfloat16 fs[];

    const int tid = threadIdx.x, lane = tid & 31, w = tid >> 5;   // 4 warps
    const int g = lane >> 2, t4 = lane & 3;
    const int bh = blockIdx.y, q0 = blockIdx.x * 128;

    const __nv_bfloat16* qp = g_q + ((size_t)bh*S_ + q0)*D_;
    const __nv_bfloat16* kp = g_k + (size_t)bh*S_*D_;
    const __nv_bfloat16* vp = g_v + (size_t)bh*S_*D_;

    const unsigned ONESB[2] = {0x3F803F80u, 0x3F803F80u};  // bf16 1.0 x2 (B frag)

    #define KV_ISSUE(KV, BUF) { \
        _Pragma("unroll") for (int i = 0; i < 4; i++){ \
            int idx = tid + 128*i; int r = idx >> 3, c = (idx & 7) * 8; \
            cpa16(sptr(&fs[FK0 + (BUF)*KVBUF + r*FSTR + c]), kp + (size_t)((KV) + r)*D_ + c); \
            cpa16(sptr(&fs[FV0 + (BUF)*KVBUF + r*FSTR + c]), vp + (size_t)((KV) + r)*D_ + c); \
        } }

    #define LDK(BUF, S, KB) { \
        _Pragma("unroll") for (int nb = 0; nb < 4; nb++){ \
            int row = nb*16 + ((lane & 16) >> 1) + (lane & 7); \
            int col = (S)*16 + (lane & 8); \
            ldsm4(KB[2*nb][0], KB[2*nb][1], KB[2*nb+1][0], KB[2*nb+1][1], \
                  sptr(&fs[FK0 + (BUF)*KVBUF + row*FSTR + col])); } }

    #define LDV(BUF, S, VB) { \
        _Pragma("unroll") for (int nb = 0; nb < 4; nb++){ \
            int kr = (S)*16 + (lane & 15); \
            int nc = nb*16 + ((lane & 16) >> 1); \
            ldsm4t(VB[2*nb][0], VB[2*nb][1], VB[2*nb+1][0], VB[2*nb+1][1], \
                   sptr(&fs[FV0 + (BUF)*KVBUF + kr*FSTR + nc])); } }

    // prologue: Q + KV0 in group0, KV1 in group1, KV2 in group2
    #pragma unroll
    for (int i = 0; i < 8; i++){
        int idx = tid + 128*i; int r = idx >> 3, c = (idx & 7) * 8;
        cpa16(sptr(&fs[FQ0 + r*FSTR + c]), qp + (size_t)r*D_ + c);
    }
    KV_ISSUE(0, 0);   cpa_commit();
    KV_ISSUE(64, 1);  cpa_commit();
    KV_ISSUE(128, 2); cpa_commit();

    cpa_wait<2>();   // Q + KV0 arrived
    __syncthreads();

    // Q fragments for rows [32w, 32w+32): qf[s][mi]
    const int r0 = w*32 + g;
    unsigned qf[4][2][4];
    #pragma unroll
    for (int s = 0; s < 4; s++)
        #pragma unroll
        for (int mi = 0; mi < 2; mi++)
            ldsm4(qf[s][mi][0], qf[s][mi][1], qf[s][mi][2], qf[s][mi][3],
                  sptr(&fs[FQ0 + (w*32 + mi*16 + (lane & 15))*FSTR + s*16 + ((lane & 16) >> 1)]));

    float acc_o[2][8][4] = {};
    float acc_l[2][4] = {};   // row-sum accumulator via ones-MMA
    float mr[2][2] = {{-CUDART_INF_F, -CUDART_INF_F}, {-CUDART_INF_F, -CUDART_INF_F}};

    #pragma unroll 1
    for (int t = 0; t < NT; t++){
        const int buf = t & 3;
        if (t + 3 < NT) KV_ISSUE((t+3)*64, (t+3) & 3);
        cpa_commit();

        // S = Q @ K^T : 32 rows x 64 cols per warp
        float sc[2][8][4] = {};
        {
            unsigned kb[2][8][2];
            LDK(buf, 0, kb[0]);
            #pragma unroll
            for (int s = 0; s < 4; s++){
                if (s < 3) LDK(buf, s+1, kb[(s+1)&1]);
                #pragma unroll
                for (int mi = 0; mi < 2; mi++)
                #pragma unroll
                for (int ni = 0; ni < 8; ni++)
                    mma16(sc[mi][ni], qf[s][mi], kb[s&1][ni]);
            }
        }

        // online softmax (log2 domain) + pack P into PV A-fragments
        unsigned pa[4][2][4];
        #pragma unroll
        for (int mi = 0; mi < 2; mi++){
            float tm0 = -CUDART_INF_F, tm1 = -CUDART_INF_F;
            #pragma unroll
            for (int ni = 0; ni < 8; ni++){
                tm0 = fmaxf(tm0, fmaxf(sc[mi][ni][0], sc[mi][ni][1]));
                tm1 = fmaxf(tm1, fmaxf(sc[mi][ni][2], sc[mi][ni][3]));
            }
            tm0 = fmaxf(tm0, __shfl_xor_sync(0xffffffffu, tm0, 1));
            tm0 = fmaxf(tm0, __shfl_xor_sync(0xffffffffu, tm0, 2));
            tm1 = fmaxf(tm1, __shfl_xor_sync(0xffffffffu, tm1, 1));
            tm1 = fmaxf(tm1, __shfl_xor_sync(0xffffffffu, tm1, 2));
            float mn0 = fmaxf(mr[mi][0], tm0), mn1 = fmaxf(mr[mi][1], tm1);
            float al0 = ex2(mr[mi][0] - mn0), al1 = ex2(mr[mi][1] - mn1);
            mr[mi][0] = mn0; mr[mi][1] = mn1;

            #pragma unroll
            for (int s = 0; s < 4; s++){
                float p00 = ex2(sc[mi][2*s  ][0] - mn0), p01 = ex2(sc[mi][2*s  ][1] - mn0);
                float p02 = ex2(sc[mi][2*s  ][2] - mn1), p03 = ex2(sc[mi][2*s  ][3] - mn1);
                float p10 = ex2(sc[mi][2*s+1][0] - mn0), p11 = ex2(sc[mi][2*s+1][1] - mn0);
                float p12 = ex2(sc[mi][2*s+1][2] - mn1), p13 = ex2(sc[mi][2*s+1][3] - mn1);
                pa[s][mi][0] = pkbf(p00, p01);
                pa[s][mi][1] = pkbf(p02, p03);
                pa[s][mi][2] = pkbf(p10, p11);
                pa[s][mi][3] = pkbf(p12, p13);
            }
            #pragma unroll
            for (int ni = 0; ni < 8; ni++){
                acc_o[mi][ni][0] *= al0; acc_o[mi][ni][1] *= al0;
                acc_o[mi][ni][2] *= al1; acc_o[mi][ni][3] *= al1;
            }
            acc_l[mi][0] *= al0; acc_l[mi][1] *= al0;
            acc_l[mi][2] *= al1; acc_l[mi][3] *= al1;
        }

        // O += P @ V ; l += P @ 1 (ones-column MMA)
        {
            unsigned vb[2][8][2];
            LDV(buf, 0, vb[0]);
            #pragma unroll
            for (int s = 0; s < 4; s++){
                if (s < 3) LDV(buf, s+1, vb[(s+1)&1]);
                #pragma unroll
                for (int mi = 0; mi < 2; mi++){
                    #pragma unroll
                    for (int ni = 0; ni < 8; ni++)
                        mma16(acc_o[mi][ni], pa[s][mi], vb[s&1][ni]);
                    mma16(acc_l[mi], pa[s][mi], ONESB);
                }
            }
        }

        if (t < NT - 1){
            cpa_wait<2>();
            __syncthreads();
        }
    }
    #undef KV_ISSUE
    #undef LDK
    #undef LDV

    int b = bh >> 4, h = bh & 15;
    #pragma unroll
    for (int mi = 0; mi < 2; mi++){
        float inv0 = 1.f / acc_l[mi][0], inv1 = 1.f / acc_l[mi][2];
        int row = q0 + r0 + mi*16;
        #pragma unroll
        for (int ni = 0; ni < 8; ni++){
            int d = ni*8 + t4*2;
            unsigned p0 = pkbf(acc_o[mi][ni][0]*inv0, acc_o[mi][ni][1]*inv0);
            unsigned p1 = pkbf(acc_o[mi][ni][2]*inv1, acc_o[mi][ni][3]*inv1);
            *reinterpret_cast<unsigned*>(&g_attn[((size_t)b*S_ + row    )*E_ + h*64 + d]) = p0;
            *reinterpret_cast<unsigned*>(&g_attn[((size_t)b*S_ + row + 8)*E_ + h*64 + d]) = p1;
        }
    }
}

// ---------------- LayerNorm over g_y rows -> d_out ----------------
__global__ void __launch_bounds__(256)
ln_kernel(const float* __restrict__ gamma, const float* __restrict__ beta,
          float* __restrict__ out)
{
    __shared__ float red[8];
    const int row = blockIdx.x, tid = threadIdx.x;
    const int lane = tid & 31, wid = tid >> 5;
    const float* y = g_y + (size_t)row*E_;

    float4 v = *reinterpret_cast<const float4*>(y + tid*4);
    float s = v.x + v.y + v.z + v.w;
    #pragma unroll
    for (int o = 16; o > 0; o >>= 1) s += __shfl_xor_sync(0xffffffffu, s, o);
    if (lane == 0) red[wid] = s;
    __syncthreads();
    float tot = red[0];
    #pragma unroll
    for (int i = 1; i < 8; i++) tot += red[i];
    float mean = tot * (1.f / 1024.f);

    float d0 = v.x - mean, d1 = v.y - mean, d2 = v.z - mean, d3 = v.w - mean;
    float s2 = d0*d0 + d1*d1 + d2*d2 + d3*d3;
    #pragma unroll
    for (int o = 16; o > 0; o >>= 1) s2 += __shfl_xor_sync(0xffffffffu, s2, o);
    __syncthreads();
    if (lane == 0) red[wid] = s2;
    __syncthreads();
    float tot2 = red[0];
    #pragma unroll
    for (int i = 1; i < 8; i++) tot2 += red[i];
    float rs = rsqrtf(tot2 * (1.f / 1024.f) + 1e-6f);

    const int c = tid * 4;
    float* op = out + (size_t)row*E_ + c;
    op[0] = d0 * rs * gamma[c + 0] + beta[c + 0];
    op[1] = d1 * rs * gamma[c + 1] + beta[c + 1];
    op[2] = d2 * rs * gamma[c + 2] + beta[c + 2];
    op[3] = d3 * rs * gamma[c + 3] + beta[c + 3];
}

// ---------------- launch ----------------
extern "C" void kernel_launch(void* const* d_in, const int* in_sizes, int n_in,
                              void* d_out, int out_size)
{
    const float* inputs = (const float*)d_in[0];
    const float* wq = (const float*)d_in[1];
    const float* bq = (const float*)d_in[2];
    const float* wk = (const float*)d_in[3];
    const float* bk = (const float*)d_in[4];
    const float* wv = (const float*)d_in[5];
    const float* bv = (const float*)d_in[6];
    const float* wo = (const float*)d_in[7];
    const float* bo = (const float*)d_in[8];
    const float* gamma = (const float*)d_in[9];
    const float* beta  = (const float*)d_in[10];
    float* out = (float*)d_out;

    cudaFuncSetAttribute(flash_kernel, cudaFuncAttributeMaxDynamicSharedMemorySize, FLASH_SMEM);
    cudaFuncSetAttribute(gemm_kernel<0>, cudaFuncAttributeMaxDynamicSharedMemorySize, GEMM_SMEM);
    cudaFuncSetAttribute(gemm_kernel<3>, cudaFuncAttributeMaxDynamicSharedMemorySize, GEMM_SMEM);

    const int ncvt = NX4 + 4*NW4;
    cvt_kernel<<<(ncvt + 255)/256, 256>>>(inputs, wq, wk, wv, wo);

    gemm_kernel<0><<<dim3(24, M_/128), 128, GEMM_SMEM>>>(bq, bk, bv, nullptr);
    flash_kernel<<<dim3(S_/128, B_*H_), 128, FLASH_SMEM>>>();
    gemm_kernel<3><<<dim3(8, M_/128), 128, GEMM_SMEM>>>(bo, nullptr, nullptr, inputs);
    ln_kernel<<<M_, 256>>>(gamma, beta, out);
}

// round 16
// speedup vs baseline: 1.0304x; 1.0304x over previous
#include <cuda_runtime.h>
#include <cuda_bf16.h>
#include <cstdint>
#include <math_constants.h>

#define B_ 4
#define S_ 2048
#define E_ 1024
#define H_ 16
#define D_ 64
#define M_ (B_*S_)

// ---------------- scratch (static device globals; no allocation) ----------------
__device__ __nv_bfloat16 g_x[(size_t)M_*E_];
__device__ __nv_bfloat16 g_wq[(size_t)E_*E_];
__device__ __nv_bfloat16 g_wk[(size_t)E_*E_];
__device__ __nv_bfloat16 g_wv[(size_t)E_*E_];
__device__ __nv_bfloat16 g_wo[(size_t)E_*E_];
__device__ __nv_bfloat16 g_q[(size_t)B_*H_*S_*D_];   // pre-scaled by log2(e)/8
__device__ __nv_bfloat16 g_k[(size_t)B_*H_*S_*D_];
__device__ __nv_bfloat16 g_v[(size_t)B_*H_*S_*D_];
__device__ __nv_bfloat16 g_attn[(size_t)M_*E_];
__device__ float g_y[(size_t)M_*E_];

// ---------------- helpers ----------------
__device__ __forceinline__ unsigned pkbf(float lo, float hi){
    unsigned r; asm("cvt.rn.bf16x2.f32 %0, %1, %2;" : "=r"(r) : "f"(hi), "f"(lo)); return r;
}
__device__ __forceinline__ float ex2(float x){
    float r; asm("ex2.approx.f32 %0, %1;" : "=f"(r) : "f"(x)); return r;
}
__device__ __forceinline__ void mma16(float* c, const unsigned* a, const unsigned* b){
    asm volatile(
        "mma.sync.aligned.m16n8k16.row.col.f32.bf16.bf16.f32 "
        "{%0,%1,%2,%3},{%4,%5,%6,%7},{%8,%9},{%0,%1,%2,%3};"
        : "+f"(c[0]), "+f"(c[1]), "+f"(c[2]), "+f"(c[3])
        : "r"(a[0]), "r"(a[1]), "r"(a[2]), "r"(a[3]), "r"(b[0]), "r"(b[1]));
}
__device__ __forceinline__ unsigned sptr(const void* p){
    return (unsigned)__cvta_generic_to_shared(p);
}
__device__ __forceinline__ void ldsm4(unsigned& r0, unsigned& r1, unsigned& r2, unsigned& r3, unsigned a){
    asm volatile("ldmatrix.sync.aligned.m8n8.x4.shared.b16 {%0,%1,%2,%3}, [%4];"
        : "=r"(r0), "=r"(r1), "=r"(r2), "=r"(r3) : "r"(a));
}
__device__ __forceinline__ void ldsm4t(unsigned& r0, unsigned& r1, unsigned& r2, unsigned& r3, unsigned a){
    asm volatile("ldmatrix.sync.aligned.m8n8.x4.trans.shared.b16 {%0,%1,%2,%3}, [%4];"
        : "=r"(r0), "=r"(r1), "=r"(r2), "=r"(r3) : "r"(a));
}
__device__ __forceinline__ void cpa16(unsigned s, const void* g){
    asm volatile("cp.async.cg.shared.global [%0], [%1], 16;" :: "r"(s), "l"(g));
}
__device__ __forceinline__ void cpa_commit(){ asm volatile("cp.async.commit_group;"); }
template<int N> __device__ __forceinline__ void cpa_wait(){
    asm volatile("cp.async.wait_group %0;" :: "n"(N));
}

// ---------------- fused fp32 -> bf16 conversion (inputs + 4 weights) ----------------
#define NX4 ((M_*E_)/4)
#define NW4 ((E_*E_)/4)
__global__ void __launch_bounds__(256)
cvt_kernel(const float* __restrict__ x,  const float* __restrict__ wq,
           const float* __restrict__ wk, const float* __restrict__ wv,
           const float* __restrict__ wo)
{
    int i = blockIdx.x * blockDim.x + threadIdx.x;
    const float* src; __nv_bfloat16* dst; int off;
    if (i < NX4) { src = x; dst = g_x; off = i; }
    else {
        int j = i - NX4; int w = j / NW4; off = j - w*NW4;
        src = (w == 0) ? wq : (w == 1) ? wk : (w == 2) ? wv : wo;
        dst = (w == 0) ? g_wq : (w == 1) ? g_wk : (w == 2) ? g_wv : g_wo;
    }
    float4 v = reinterpret_cast<const float4*>(src)[off];
    reinterpret_cast<uint2*>(dst)[off] = make_uint2(pkbf(v.x, v.y), pkbf(v.z, v.w));
}

// ---------------- GEMM: 128x128x32 tile, 4 warps (2x2), warp tile 64x64 ----------------
// (R13 configuration — locked: 4-stage cp.async, &3 indexing, 2 CTAs/SM)
#define GSTAGES 4
#define AS_ELEM 5120   // 128*40
#define BS_ELEM 4352   // 32*136
#define GEMM_SMEM ((GSTAGES*(AS_ELEM + BS_ELEM)) * 2)
#define ASO(st) ((st)*AS_ELEM)
#define BSO(st) (GSTAGES*AS_ELEM + (st)*BS_ELEM)

// MODE 0: fused QKV (grid.x = 24: [qkv sel][8 col blocks]); MODE 3: O-proj
template<int MODE>
__global__ void __launch_bounds__(128, 2)
gemm_kernel(const float* __restrict__ b0p, const float* __restrict__ b1p,
            const float* __restrict__ b2p, const float* __restrict__ resid)
{
    extern __shared__ __align__(16) __nv_bfloat16 sm[];

    const int tid = threadIdx.x, lane = tid & 31;
    const int g = lane >> 2, t4 = lane & 3;
    const int wid = tid >> 5, wm = wid & 1, wn = wid >> 1;   // 2 x 2 warp grid
    const int sel = (MODE == 0) ? (blockIdx.x >> 3) : 0;
    const int bm = blockIdx.y * 128, bn = (MODE == 0) ? (blockIdx.x & 7) * 128 : blockIdx.x * 128;

    const __nv_bfloat16* Ap = (MODE == 3) ? g_attn : g_x;
    const __nv_bfloat16* Wp = (MODE == 3) ? g_wo :
                              (sel == 0) ? g_wq : (sel == 1) ? g_wk : g_wv;
    const float* bias = (MODE == 3) ? b0p : (sel == 0) ? b0p : (sel == 1) ? b1p : b2p;

    float acc[4][8][4] = {};

    #define G_ISSUE(KT, ST) { \
        _Pragma("unroll") for (int i = 0; i < 4; i++){ \
            int idx = tid + 128*i; \
            int ar = idx >> 2, ac = (idx & 3) * 8; \
            cpa16(sptr(&sm[ASO(ST) + ar*40 + ac]), Ap + (size_t)(bm + ar)*E_ + (KT) + ac); \
            int br = idx >> 4, bc = (idx & 15) * 8; \
            cpa16(sptr(&sm[BSO(ST) + br*136 + bc]), Wp + (size_t)((KT) + br)*E_ + bn + bc); \
        } \
        cpa_commit(); }

    G_ISSUE(0, 0);
    G_ISSUE(32, 1);
    G_ISSUE(64, 2);

    cpa_wait<2>();
    __syncthreads();

    #pragma unroll 1
    for (int kt = 0; kt < 32; kt++){
        const int st = kt & 3;
        if (kt + 3 < 32) G_ISSUE((kt+3)*32, (kt+3) & 3);

        #pragma unroll
        for (int s = 0; s < 2; s++){
            unsigned af[4][4];
            #pragma unroll
            for (int mi = 0; mi < 4; mi++)
                ldsm4(af[mi][0], af[mi][1], af[mi][2], af[mi][3],
                      sptr(&sm[ASO(st) + (wm*64 + mi*16 + (lane & 15))*40 + s*16 + ((lane & 16) >> 1)]));
            unsigned bfr[8][2];
            #pragma unroll
            for (int nb = 0; nb < 4; nb++)
                ldsm4t(bfr[2*nb][0], bfr[2*nb][1], bfr[2*nb+1][0], bfr[2*nb+1][1],
                       sptr(&sm[BSO(st) + (s*16 + (lane & 15))*136 + wn*64 + nb*16 + ((lane & 16) >> 1)]));
            #pragma unroll
            for (int mi = 0; mi < 4; mi++)
            #pragma unroll
            for (int ni = 0; ni < 8; ni++)
                mma16(acc[mi][ni], af[mi], bfr[ni]);
        }

        if (kt + 1 < 32){
            cpa_wait<2>();
            __syncthreads();
        }
    }
    #undef G_ISSUE

    const float qsc = (MODE == 0 && sel == 0) ? 0.125f*1.44269504f : 1.0f;
    #pragma unroll
    for (int mi = 0; mi < 4; mi++)
    #pragma unroll
    for (int ni = 0; ni < 8; ni++){
        int row = bm + wm*64 + mi*16 + g;
        int col = bn + wn*64 + ni*8 + t4*2;
        float b0 = bias[col], b1 = bias[col+1];
        if (MODE == 3){
            float2 r0 = *reinterpret_cast<const float2*>(&resid[(size_t)row*E_ + col]);
            float2 r1 = *reinterpret_cast<const float2*>(&resid[(size_t)(row+8)*E_ + col]);
            *reinterpret_cast<float2*>(&g_y[(size_t)row*E_ + col]) =
                make_float2(acc[mi][ni][0] + b0 + r0.x, acc[mi][ni][1] + b1 + r0.y);
            *reinterpret_cast<float2*>(&g_y[(size_t)(row+8)*E_ + col]) =
                make_float2(acc[mi][ni][2] + b0 + r1.x, acc[mi][ni][3] + b1 + r1.y);
        } else {
            __nv_bfloat16* op = (sel == 0) ? g_q : (sel == 1) ? g_k : g_v;
            int h = col >> 6, d = col & 63;
            unsigned p0 = pkbf((acc[mi][ni][0] + b0)*qsc, (acc[mi][ni][1] + b1)*qsc);
            unsigned p1 = pkbf((acc[mi][ni][2] + b0)*qsc, (acc[mi][ni][3] + b1)*qsc);
            int b = row >> 11, s0 = row & (S_-1);
            size_t base = (((size_t)(b*H_ + h))*S_);
            *reinterpret_cast<unsigned*>(&op[(base + s0    )*D_ + d]) = p0;
            *reinterpret_cast<unsigned*>(&op[(base + s0 + 8)*D_ + d]) = p1;
        }
    }
}

// ---------------- flash attention: Br=128, Bc=64, 4 warps x 32 Q-rows ----------------
// R15's flash (measured ~5us better): 4 KV buffers (&3), prefetch distance 3, wait<2>.
// l via ones-column MMA.
#define FQ0 0
#define FK0 9216
#define FV0 27648
#define FSTR 72
#define KVBUF 4608
#define NT (S_/64)
#define FLASH_SMEM ((FV0 + 4*KVBUF) * 2)

__global__ void __launch_bounds__(128, 2)
flash_kernel()
{
    extern __shared__ __align__(16) __nv_bfloat16 fs[];

    const int tid = threadIdx.x, lane = tid & 31, w = tid >> 5;   // 4 warps
    const int g = lane >> 2, t4 = lane & 3;
    const int bh = blockIdx.y, q0 = blockIdx.x * 128;

    const __nv_bfloat16* qp = g_q + ((size_t)bh*S_ + q0)*D_;
    const __nv_bfloat16* kp = g_k + (size_t)bh*S_*D_;
    const __nv_bfloat16* vp = g_v + (size_t)bh*S_*D_;

    const unsigned ONESB[2] = {0x3F803F80u, 0x3F803F80u};  // bf16 1.0 x2 (B frag)

    #define KV_ISSUE(KV, BUF) { \
        _Pragma("unroll") for (int i = 0; i < 4; i++){ \
            int idx = tid + 128*i; int r = idx >> 3, c = (idx & 7) * 8; \
            cpa16(sptr(&fs[FK0 + (BUF)*KVBUF + r*FSTR + c]), kp + (size_t)((KV) + r)*D_ + c); \
            cpa16(sptr(&fs[FV0 + (BUF)*KVBUF + r*FSTR + c]), vp + (size_t)((KV) + r)*D_ + c); \
        } }

    #define LDK(BUF, S, KB) { \
        _Pragma("unroll") for (int nb = 0; nb < 4; nb++){ \
            int row = nb*16 + ((lane & 16) >> 1) + (lane & 7); \
            int col = (S)*16 + (lane & 8); \
            ldsm4(KB[2*nb][0], KB[2*nb][1], KB[2*nb+1][0], KB[2*nb+1][1], \
                  sptr(&fs[FK0 + (BUF)*KVBUF + row*FSTR + col])); } }

    #define LDV(BUF, S, VB) { \
        _Pragma("unroll") for (int nb = 0; nb < 4; nb++){ \
            int kr = (S)*16 + (lane & 15); \
            int nc = nb*16 + ((lane & 16) >> 1); \
            ldsm4t(VB[2*nb][0], VB[2*nb][1], VB[2*nb+1][0], VB[2*nb+1][1], \
                   sptr(&fs[FV0 + (BUF)*KVBUF + kr*FSTR + nc])); } }

    // prologue: Q + KV0 in group0, KV1 in group1, KV2 in group2
    #pragma unroll
    for (int i = 0; i < 8; i++){
        int idx = tid + 128*i; int r = idx >> 3, c = (idx & 7) * 8;
        cpa16(sptr(&fs[FQ0 + r*FSTR + c]), qp + (size_t)r*D_ + c);
    }
    KV_ISSUE(0, 0);   cpa_commit();
    KV_ISSUE(64, 1);  cpa_commit();
    KV_ISSUE(128, 2); cpa_commit();

    cpa_wait<2>();   // Q + KV0 arrived
    __syncthreads();

    // Q fragments for rows [32w, 32w+32): qf[s][mi]
    const int r0 = w*32 + g;
    unsigned qf[4][2][4];
    #pragma unroll
    for (int s = 0; s < 4; s++)
        #pragma unroll
        for (int mi = 0; mi < 2; mi++)
            ldsm4(qf[s][mi][0], qf[s][mi][1], qf[s][mi][2], qf[s][mi][3],
                  sptr(&fs[FQ0 + (w*32 + mi*16 + (lane & 15))*FSTR + s*16 + ((lane & 16) >> 1)]));

    float acc_o[2][8][4] = {};
    float acc_l[2][4] = {};   // row-sum accumulator via ones-MMA
    float mr[2][2] = {{-CUDART_INF_F, -CUDART_INF_F}, {-CUDART_INF_F, -CUDART_INF_F}};

    #pragma unroll 1
    for (int t = 0; t < NT; t++){
        const int buf = t & 3;
        if (t + 3 < NT) KV_ISSUE((t+3)*64, (t+3) & 3);
        cpa_commit();

        // S = Q @ K^T : 32 rows x 64 cols per warp
        float sc[2][8][4] = {};
        {
            unsigned kb[2][8][2];
            LDK(buf, 0, kb[0]);
            #pragma unroll
            for (int s = 0; s < 4; s++){
                if (s < 3) LDK(buf, s+1, kb[(s+1)&1]);
                #pragma unroll
                for (int mi = 0; mi < 2; mi++)
                #pragma unroll
                for (int ni = 0; ni < 8; ni++)
                    mma16(sc[mi][ni], qf[s][mi], kb[s&1][ni]);
            }
        }

        // online softmax (log2 domain) + pack P into PV A-fragments
        unsigned pa[4][2][4];
        #pragma unroll
        for (int mi = 0; mi < 2; mi++){
            float tm0 = -CUDART_INF_F, tm1 = -CUDART_INF_F;
            #pragma unroll
            for (int ni = 0; ni < 8; ni++){
                tm0 = fmaxf(tm0, fmaxf(sc[mi][ni][0], sc[mi][ni][1]));
                tm1 = fmaxf(tm1, fmaxf(sc[mi][ni][2], sc[mi][ni][3]));
            }
            tm0 = fmaxf(tm0, __shfl_xor_sync(0xffffffffu, tm0, 1));
            tm0 = fmaxf(tm0, __shfl_xor_sync(0xffffffffu, tm0, 2));
            tm1 = fmaxf(tm1, __shfl_xor_sync(0xffffffffu, tm1, 1));
            tm1 = fmaxf(tm1, __shfl_xor_sync(0xffffffffu, tm1, 2));
            float mn0 = fmaxf(mr[mi][0], tm0), mn1 = fmaxf(mr[mi][1], tm1);
            float al0 = ex2(mr[mi][0] - mn0), al1 = ex2(mr[mi][1] - mn1);
            mr[mi][0] = mn0; mr[mi][1] = mn1;

            #pragma unroll
            for (int s = 0; s < 4; s++){
                float p00 = ex2(sc[mi][2*s  ][0] - mn0), p01 = ex2(sc[mi][2*s  ][1] - mn0);
                float p02 = ex2(sc[mi][2*s  ][2] - mn1), p03 = ex2(sc[mi][2*s  ][3] - mn1);
                float p10 = ex2(sc[mi][2*s+1][0] - mn0), p11 = ex2(sc[mi][2*s+1][1] - mn0);
                float p12 = ex2(sc[mi][2*s+1][2] - mn1), p13 = ex2(sc[mi][2*s+1][3] - mn1);
                pa[s][mi][0] = pkbf(p00, p01);
                pa[s][mi][1] = pkbf(p02, p03);
                pa[s][mi][2] = pkbf(p10, p11);
                pa[s][mi][3] = pkbf(p12, p13);
            }
            #pragma unroll
            for (int ni = 0; ni < 8; ni++){
                acc_o[mi][ni][0] *= al0; acc_o[mi][ni][1] *= al0;
                acc_o[mi][ni][2] *= al1; acc_o[mi][ni][3] *= al1;
            }
            acc_l[mi][0] *= al0; acc_l[mi][1] *= al0;
            acc_l[mi][2] *= al1; acc_l[mi][3] *= al1;
        }

        // O += P @ V ; l += P @ 1 (ones-column MMA)
        {
            unsigned vb[2][8][2];
            LDV(buf, 0, vb[0]);
            #pragma unroll
            for (int s = 0; s < 4; s++){
                if (s < 3) LDV(buf, s+1, vb[(s+1)&1]);
                #pragma unroll
                for (int mi = 0; mi < 2; mi++){
                    #pragma unroll
                    for (int ni = 0; ni < 8; ni++)
                        mma16(acc_o[mi][ni], pa[s][mi], vb[s&1][ni]);
                    mma16(acc_l[mi], pa[s][mi], ONESB);
                }
            }
        }

        if (t < NT - 1){
            cpa_wait<2>();
            __syncthreads();
        }
    }
    #undef KV_ISSUE
    #undef LDK
    #undef LDV

    int b = bh >> 4, h = bh & 15;
    #pragma unroll
    for (int mi = 0; mi < 2; mi++){
        float inv0 = 1.f / acc_l[mi][0], inv1 = 1.f / acc_l[mi][2];
        int row = q0 + r0 + mi*16;
        #pragma unroll
        for (int ni = 0; ni < 8; ni++){
            int d = ni*8 + t4*2;
            unsigned p0 = pkbf(acc_o[mi][ni][0]*inv0, acc_o[mi][ni][1]*inv0);
            unsigned p1 = pkbf(acc_o[mi][ni][2]*inv1, acc_o[mi][ni][3]*inv1);
            *reinterpret_cast<unsigned*>(&g_attn[((size_t)b*S_ + row    )*E_ + h*64 + d]) = p0;
            *reinterpret_cast<unsigned*>(&g_attn[((size_t)b*S_ + row + 8)*E_ + h*64 + d]) = p1;
        }
    }
}

// ---------------- LayerNorm over g_y rows -> d_out ----------------
__global__ void __launch_bounds__(256)
ln_kernel(const float* __restrict__ gamma, const float* __restrict__ beta,
          float* __restrict__ out)
{
    __shared__ float red[8];
    const int row = blockIdx.x, tid = threadIdx.x;
    const int lane = tid & 31, wid = tid >> 5;
    const float* y = g_y + (size_t)row*E_;

    float4 v = *reinterpret_cast<const float4*>(y + tid*4);
    float s = v.x + v.y + v.z + v.w;
    #pragma unroll
    for (int o = 16; o > 0; o >>= 1) s += __shfl_xor_sync(0xffffffffu, s, o);
    if (lane == 0) red[wid] = s;
    __syncthreads();
    float tot = red[0];
    #pragma unroll
    for (int i = 1; i < 8; i++) tot += red[i];
    float mean = tot * (1.f / 1024.f);

    float d0 = v.x - mean, d1 = v.y - mean, d2 = v.z - mean, d3 = v.w - mean;
    float s2 = d0*d0 + d1*d1 + d2*d2 + d3*d3;
    #pragma unroll
    for (int o = 16; o > 0; o >>= 1) s2 += __shfl_xor_sync(0xffffffffu, s2, o);
    __syncthreads();
    if (lane == 0) red[wid] = s2;
    __syncthreads();
    float tot2 = red[0];
    #pragma unroll
    for (int i = 1; i < 8; i++) tot2 += red[i];
    float rs = rsqrtf(tot2 * (1.f / 1024.f) + 1e-6f);

    const int c = tid * 4;
    float* op = out + (size_t)row*E_ + c;
    op[0] = d0 * rs * gamma[c + 0] + beta[c + 0];
    op[1] = d1 * rs * gamma[c + 1] + beta[c + 1];
    op[2] = d2 * rs * gamma[c + 2] + beta[c + 2];
    op[3] = d3 * rs * gamma[c + 3] + beta[c + 3];
}

// ---------------- launch ----------------
extern "C" void kernel_launch(void* const* d_in, const int* in_sizes, int n_in,
                              void* d_out, int out_size)
{
    const float* inputs = (const float*)d_in[0];
    const float* wq = (const float*)d_in[1];
    const float* bq = (const float*)d_in[2];
    const float* wk = (const float*)d_in[3];
    const float* bk = (const float*)d_in[4];
    const float* wv = (const float*)d_in[5];
    const float* bv = (const float*)d_in[6];
    const float* wo = (const float*)d_in[7];
    const float* bo = (const float*)d_in[8];
    const float* gamma = (const float*)d_in[9];
    const float* beta  = (const float*)d_in[10];
    float* out = (float*)d_out;

    cudaFuncSetAttribute(flash_kernel, cudaFuncAttributeMaxDynamicSharedMemorySize, FLASH_SMEM);
    cudaFuncSetAttribute(gemm_kernel<0>, cudaFuncAttributeMaxDynamicSharedMemorySize, GEMM_SMEM);
    cudaFuncSetAttribute(gemm_kernel<3>, cudaFuncAttributeMaxDynamicSharedMemorySize, GEMM_SMEM);

    const int ncvt = NX4 + 4*NW4;
    cvt_kernel<<<(ncvt + 255)/256, 256>>>(inputs, wq, wk, wv, wo);

    gemm_kernel<0><<<dim3(24, M_/128), 128, GEMM_SMEM>>>(bq, bk, bv, nullptr);
    flash_kernel<<<dim3(S_/128, B_*H_), 128, FLASH_SMEM>>>();
    gemm_kernel<3><<<dim3(8, M_/128), 128, GEMM_SMEM>>>(bo, nullptr, nullptr, inputs);
    ln_kernel<<<M_, 256>>>(gamma, beta, out);
}